// round 1
// baseline (speedup 1.0000x reference)
#include <cuda_runtime.h>
#include <cuda_bf16.h>

#define NN   800
#define CC   64
#define TRS  40
#define SPT  10
#define BUF  120
#define TT   400
#define NBLK 100
#define RPB  8      // rows per block (8 warps, 1 row per warp)
#define THREADS 256
#define KPL  25     // 800 / 32 j-values per lane

// ---------------- scratch (static device allocations; no cudaMalloc) --------
__device__ __align__(16) __nv_bfloat16 g_HT0[BUF * NN];  // transposed hE (bf16)
__device__ __align__(16) float g_XTR[TRS * NN];          // x at last step of each TR
__device__ __align__(16) float g_Xg[2 * NN];             // ping-pong x broadcast
__device__ int   g_ctr[TT];                              // per-step barrier counters
__device__ float g_rowsum[NN];                           // sum_j |sc[i,j]|
__device__ float g_rowsq[NN];                            // sum_j sc[i,j]^2
__device__ float g_invnorm;                              // 1/||sc||_F
__device__ int   g_flag64;                               // delays stored as int64?

// ---------------- per-row stats: rowsum(|sc|), rowsq(sc^2) ------------------
__global__ void k_rowstats(const float* __restrict__ sc) {
    int i = blockIdx.x, tid = threadIdx.x;
    float s1 = 0.f, s2 = 0.f;
    for (int j = tid; j < NN; j += 128) {
        float v = sc[i * NN + j];
        s1 += fabsf(v);
        s2 += v * v;
    }
    #pragma unroll
    for (int o = 16; o; o >>= 1) {
        s1 += __shfl_xor_sync(0xffffffffu, s1, o);
        s2 += __shfl_xor_sync(0xffffffffu, s2, o);
    }
    __shared__ float sh1[4], sh2[4];
    if ((tid & 31) == 0) { sh1[tid >> 5] = s1; sh2[tid >> 5] = s2; }
    __syncthreads();
    if (tid == 0) {
        g_rowsum[i] = sh1[0] + sh1[1] + sh1[2] + sh1[3];
        g_rowsq[i]  = sh2[0] + sh2[1] + sh2[2] + sh2[3];
    }
}

// ---------------- norm reduction (deterministic, single block) --------------
__global__ void k_norm() {
    int tid = threadIdx.x;
    float s = 0.f;
    for (int i = tid; i < NN; i += 256) s += g_rowsq[i];
    #pragma unroll
    for (int o = 16; o; o >>= 1) s += __shfl_xor_sync(0xffffffffu, s, o);
    __shared__ float sh[8];
    if ((tid & 31) == 0) sh[tid >> 5] = s;
    __syncthreads();
    if (tid == 0) {
        float tot = 0.f;
        #pragma unroll
        for (int w = 0; w < 8; w++) tot += sh[w];
        g_invnorm = rsqrtf(tot);
    }
}

// ---------------- prep: transpose hE -> bf16, zero counters, dtype detect ---
__global__ void k_prep2(const float* __restrict__ hE, const void* __restrict__ delays) {
    int g = blockIdx.x * blockDim.x + threadIdx.x;
    if (g < BUF * NN) {
        int m = g / NN, j = g % NN;
        // H[m][j] holds x at "absolute step" m-BUF, i.e. hE[j][BUF-1-m]
        g_HT0[g] = __float2bfloat16(hE[j * BUF + (BUF - 1 - m)]);
    }
    if (g < TT) g_ctr[g] = 0;
    if (g == 0) {
        const int* p = (const int*)delays;
        int any = 0;
        for (int k = 0; k < 100; k++) any |= p[2 * k + 1];
        g_flag64 = (any == 0) ? 1 : 0;  // int64: high words all zero
    }
}

// ---------------- main persistent integration kernel ------------------------
__global__ void __launch_bounds__(THREADS, 1)
k_main(const float* __restrict__ external, const float* __restrict__ hx,
       const float* __restrict__ sc, const float* __restrict__ noise,
       const void* __restrict__ delays) {
    extern __shared__ __align__(16) unsigned char smem_raw[];
    __nv_bfloat16* Hs = (__nv_bfloat16*)smem_raw;   // [BUF][NN] bf16 history

    const int tid = threadIdx.x;
    const int lane = tid & 31;
    const int wrp = tid >> 5;
    const int i = blockIdx.x * RPB + wrp;           // this warp's node row

    // stage full history into shared (vectorized, coalesced)
    {
        const uint4* src = (const uint4*)g_HT0;
        uint4* dst = (uint4*)Hs;
        for (int idx = tid; idx < (BUF * NN * 2) / 16; idx += THREADS)
            dst[idx] = src[idx];
    }

    // step-invariant per-lane constants in registers
    float wreg[KPL];
    int   dreg[KPL];
    const int f64 = g_flag64;
    const int* dp = (const int*)delays;
    #pragma unroll
    for (int k = 0; k < KPL; k++) {
        int j = lane + 32 * k;
        int e = i * NN + j;
        wreg[k] = fabsf(sc[e]);
        dreg[k] = f64 ? dp[2 * e] : dp[e];          // little-endian low word
    }
    const float invn = g_invnorm;
    const float Gn  = 500.0f * invn;
    const float grs = Gn * g_rowsum[i];
    float x = hx[2 * i], y = hx[2 * i + 1];
    __syncthreads();

    for (int t = 0; t < TT; t++) {
        // append x(t-1) (from all blocks) into local shared history
        if (t) {
            int slotw = (t - 1) % BUF;
            const float4* xs = (const float4*)(g_Xg + ((t - 1) & 1) * NN);
            __nv_bfloat162* drow = (__nv_bfloat162*)(Hs + slotw * NN);
            for (int idx = tid; idx < NN / 4; idx += THREADS) {
                float4 v = __ldcg(xs + idx);
                drow[idx * 2]     = __floats2bfloat162_rn(v.x, v.y);
                drow[idx * 2 + 1] = __floats2bfloat162_rn(v.z, v.w);
            }
            __syncthreads();
        }

        // gather-dot: LEd_raw[i] = sum_j |sc[i,j]| * x_j(t-1-d[i,j])
        const int base = (t + BUF - 1) % BUF;       // slot of x(t-1)
        float a0 = 0.f, a1 = 0.f;
        #pragma unroll
        for (int k = 0; k < KPL; k++) {
            int s = base - dreg[k];
            if (s < 0) s += BUF;
            float h = __bfloat162float(Hs[s * NN + lane + 32 * k]);
            if (k & 1) a1 = fmaf(wreg[k], h, a1);
            else       a0 = fmaf(wreg[k], h, a0);
        }
        float acc = a0 + a1;
        #pragma unroll
        for (int o = 16; o; o >>= 1) acc += __shfl_xor_sync(0xffffffffu, acc, o);

        // Hopf update (all lanes redundantly; identical values)
        float u  = __ldg(&external[i * (SPT * TRS) + (t % SPT) * TRS + (t / SPT)]);
        float2 ns = *(const float2*)&noise[(size_t)t * 2 * NN + 2 * i];
        float r2 = x * x + y * y;
        float dx = (-0.5f - r2) * x - 10.0f * y + Gn * acc - grs * x + 5.0f * u;
        float dy = (-0.5f - r2) * y + 10.0f * x;
        x = x + 1e-4f * dx + ns.x;                  // sqrt(dt)*std_in = 1.0
        y = y + 1e-4f * dy + ns.y;

        if (lane == 0) {
            __stcg(&g_Xg[(t & 1) * NN + i], x);
            if (t % SPT == SPT - 1) g_XTR[(t / SPT) * NN + i] = x;
        }

        // global step barrier (release -> counter -> acquire)
        __syncthreads();
        if (tid == 0) {
            __threadfence();
            atomicAdd(&g_ctr[t], 1);
            while (*((volatile int*)&g_ctr[t]) < NBLK) { }
            __threadfence();
        }
        __syncthreads();
    }
}

// ---------------- EEG projection: out[c][tr] = 5 * <x_tr, lm[c]> - 2 --------
__global__ void k_eeg(const float* __restrict__ lm, float* __restrict__ out) {
    int c = blockIdx.x, tr = blockIdx.y, tid = threadIdx.x;
    float s = 0.f;
    for (int i = tid; i < NN; i += 128)
        s += g_XTR[tr * NN + i] * lm[c * NN + i];
    #pragma unroll
    for (int o = 16; o; o >>= 1) s += __shfl_xor_sync(0xffffffffu, s, o);
    __shared__ float sh[4];
    if ((tid & 31) == 0) sh[tid >> 5] = s;
    __syncthreads();
    if (tid == 0) out[c * TRS + tr] = 5.0f * (sh[0] + sh[1] + sh[2] + sh[3]) - 2.0f;
}

extern "C" void kernel_launch(void* const* d_in, const int* in_sizes, int n_in,
                              void* d_out, int out_size) {
    const float* external = (const float*)d_in[0];
    const float* hx       = (const float*)d_in[1];
    const float* hE       = (const float*)d_in[2];
    const float* sc       = (const float*)d_in[3];
    const float* lm       = (const float*)d_in[4];
    const float* noise    = (const float*)d_in[5];
    const void*  delays   = d_in[6];

    cudaFuncSetAttribute(k_main, cudaFuncAttributeMaxDynamicSharedMemorySize,
                         BUF * NN * 2);

    k_rowstats<<<NN, 128>>>(sc);
    k_prep2<<<(BUF * NN + 255) / 256, 256>>>(hE, delays);
    k_norm<<<1, 256>>>();
    k_main<<<NBLK, THREADS, BUF * NN * 2>>>(external, hx, sc, noise, delays);
    k_eeg<<<dim3(CC, TRS), 128>>>(lm, (float*)d_out);
}